// round 4
// baseline (speedup 1.0000x reference)
#include <cuda_runtime.h>
#include <cstdint>

#define IMG_H 1024
#define IMG_W 1024
#define NB 8
#define HW (IMG_H * IMG_W)

// Scratch (static device globals; no runtime allocation).
// g_gmt: gradient magnitude, PIXEL-MAJOR [pix][plane] -> one 32B sector holds
//        all 8 planes of a pixel -> coalesced cross-plane gathers in kernel B.
// g_idx: quantized orientation index (0..7), plane-major.
__device__ float         g_gmt[HW * NB];
__device__ unsigned char g_idx[NB * HW];

// neighbor offsets of dir filter k (cross-correlation, -1 position):
// k: 0:E 1:SE 2:S 3:SW 4:W 5:NW 6:N 7:NE
__constant__ int c_dy[8] = {0, 1, 1, 1, 0, -1, -1, -1};
__constant__ int c_dx[8] = {1, 1, 0, -1, -1, -1, 0, 1};

// ---------------------------------------------------------------------------
// Compensated (float-float) arithmetic. All with _rn intrinsics so the result
// is identical regardless of --use_fast_math / fmad contraction choices.
// ---------------------------------------------------------------------------
__device__ __forceinline__ void two_sum(float a, float b, float& s, float& e) {
    s = __fadd_rn(a, b);
    float bv = __fsub_rn(s, a);
    e = __fadd_rn(__fsub_rn(a, __fsub_rn(s, bv)), __fsub_rn(b, bv));
}

struct DAcc { float hi, err; };
__device__ __forceinline__ void dacc_init(DAcc& A) { A.hi = 0.f; A.err = 0.f; }

// A += a*b  (a,b plain floats)
__device__ __forceinline__ void dacc_fmaff(DAcc& A, float a, float b) {
    float p = __fmul_rn(a, b);
    float e = __fmaf_rn(a, b, -p);
    float s, e2; two_sum(A.hi, p, s, e2);
    A.hi = s;
    A.err = __fadd_rn(A.err, __fadd_rn(e, e2));
}

// A += v*w  (v float-float, w plain float)
__device__ __forceinline__ void dacc_fmadf(DAcc& A, float2 v, float w) {
    float p = __fmul_rn(v.x, w);
    float e = __fmaf_rn(v.x, w, -p);
    e = __fmaf_rn(v.y, w, e);
    float s, e2; two_sum(A.hi, p, s, e2);
    A.hi = s;
    A.err = __fadd_rn(A.err, __fadd_rn(e, e2));
}

__device__ __forceinline__ float2 dacc_renorm(const DAcc& A) {
    float hi = __fadd_rn(A.hi, A.err);
    float lo = __fsub_rn(A.err, __fsub_rn(hi, A.hi));
    return make_float2(hi, lo);
}

__device__ __forceinline__ float2 df_sqr(float2 a) {
    float p = __fmul_rn(a.x, a.x);
    float e = __fmaf_rn(a.x, a.x, -p);
    e = __fmaf_rn(__fmul_rn(2.f, a.x), a.y, e);
    return make_float2(p, e);
}

__device__ __forceinline__ float2 df_add(float2 a, float2 b) {
    float s, e; two_sum(a.x, b.x, s, e);
    e = __fadd_rn(e, __fadd_rn(a.y, b.y));
    float hi = __fadd_rn(s, e);
    float lo = __fsub_rn(e, __fsub_rn(hi, s));
    return make_float2(hi, lo);
}

__device__ __forceinline__ float2 df_sqrt(float2 a) {
    if (!(a.x > 1e-37f)) {
        float h = a.x > 0.f ? a.x : 0.f;
        return make_float2(__fsqrt_rn(h), 0.f);
    }
    float y = __fsqrt_rn(a.x);
    float p = __fmul_rn(y, y);
    float e = __fmaf_rn(y, y, -p);
    float d = __fsub_rn(a.x, p);                    // near-exact residual
    float num = __fadd_rn(d, __fsub_rn(a.y, e));
    float c = __fdiv_rn(num, __fmul_rn(2.f, y));
    float hi = __fadd_rn(y, c);
    float lo = __fsub_rn(c, __fsub_rn(hi, y));
    return make_float2(hi, lo);
}

// ---------------------------------------------------------------------------
// Kernel A: per batch, per 32x32 tile: 3 channels of
//   raw -> hblur(5) -> vblur(5) -> sobel(3x3)
// All arithmetic in float-float so gm/gx/gy are correctly-rounded fp32.
// ---------------------------------------------------------------------------
__global__ __launch_bounds__(256) void canny_grad_kernel(
    const float* __restrict__ img, const float* __restrict__ gw)
{
    const int b  = blockIdx.z;
    const int x0 = blockIdx.x * 32;
    const int y0 = blockIdx.y * 32;
    const int tid = threadIdx.y * 32 + threadIdx.x;

    __shared__ float  s_raw[38][40];  // raw tile, halo 3
    __shared__ float2 s_hb[38][36];   // horizontally blurred (df), 34 cols
    __shared__ float2 s_bl[34][36];   // fully blurred (df), halo 1 for sobel

    const float g0 = gw[0], g1 = gw[1], g2 = gw[2], g3 = gw[3], g4 = gw[4];

    DAcc magA[4], gxsA[4], gysA[4];
    #pragma unroll
    for (int k = 0; k < 4; ++k) { dacc_init(magA[k]); dacc_init(gxsA[k]); dacc_init(gysA[k]); }

    for (int c = 0; c < 3; ++c) {
        const float* __restrict__ src = img + (size_t)(b * 3 + c) * HW;

        // load raw with zero padding (gaussian conv pads with zeros)
        for (int i = tid; i < 38 * 38; i += 256) {
            int r = i / 38, cc = i % 38;
            int gy = y0 - 3 + r, gx = x0 - 3 + cc;
            float v = 0.f;
            if ((unsigned)gy < IMG_H && (unsigned)gx < IMG_W) v = src[gy * IMG_W + gx];
            s_raw[r][cc] = v;
        }
        __syncthreads();

        // horizontal 5-tap (df): hb[r][cc] -> x = x0-1+cc
        for (int i = tid; i < 38 * 34; i += 256) {
            int r = i / 34, cc = i % 34;
            DAcc A; dacc_init(A);
            dacc_fmaff(A, g0, s_raw[r][cc]);
            dacc_fmaff(A, g1, s_raw[r][cc + 1]);
            dacc_fmaff(A, g2, s_raw[r][cc + 2]);
            dacc_fmaff(A, g3, s_raw[r][cc + 3]);
            dacc_fmaff(A, g4, s_raw[r][cc + 4]);
            s_hb[r][cc] = dacc_renorm(A);
        }
        __syncthreads();

        // vertical 5-tap (df); sobel sees zeros outside image -> force OOB 0
        for (int i = tid; i < 34 * 34; i += 256) {
            int r = i / 34, cc = i % 34;
            int gy = y0 - 1 + r, gx = x0 - 1 + cc;
            float2 v = make_float2(0.f, 0.f);
            if ((unsigned)gy < IMG_H && (unsigned)gx < IMG_W) {
                DAcc A; dacc_init(A);
                dacc_fmadf(A, s_hb[r][cc],     g0);
                dacc_fmadf(A, s_hb[r + 1][cc], g1);
                dacc_fmadf(A, s_hb[r + 2][cc], g2);
                dacc_fmadf(A, s_hb[r + 3][cc], g3);
                dacc_fmadf(A, s_hb[r + 4][cc], g4);
                v = dacc_renorm(A);
            }
            s_bl[r][cc] = v;
        }
        __syncthreads();

        // sobel (cross-correlation, zero padded via s_bl), df arithmetic
        const int tx = threadIdx.x;
        #pragma unroll
        for (int k = 0; k < 4; ++k) {
            int ty = threadIdx.y + k * 8;
            float2 b00 = s_bl[ty][tx],     b01 = s_bl[ty][tx + 1],     b02 = s_bl[ty][tx + 2];
            float2 b10 = s_bl[ty + 1][tx],                             b12 = s_bl[ty + 1][tx + 2];
            float2 b20 = s_bl[ty + 2][tx], b21 = s_bl[ty + 2][tx + 1], b22 = s_bl[ty + 2][tx + 2];

            DAcc GX; dacc_init(GX);
            dacc_fmadf(GX, b00,  1.f); dacc_fmadf(GX, b02, -1.f);
            dacc_fmadf(GX, b10,  2.f); dacc_fmadf(GX, b12, -2.f);
            dacc_fmadf(GX, b20,  1.f); dacc_fmadf(GX, b22, -1.f);
            float2 gx = dacc_renorm(GX);

            DAcc GY; dacc_init(GY);
            dacc_fmadf(GY, b00,  1.f); dacc_fmadf(GY, b01,  2.f); dacc_fmadf(GY, b02,  1.f);
            dacc_fmadf(GY, b20, -1.f); dacc_fmadf(GY, b21, -2.f); dacc_fmadf(GY, b22, -1.f);
            float2 gy = dacc_renorm(GY);

            float2 m = df_sqrt(df_add(df_sqr(gx), df_sqr(gy)));
            dacc_fmadf(magA[k], m, 1.f);
            dacc_fmadf(gxsA[k], gx, 1.f);
            dacc_fmadf(gysA[k], gy, 1.f);
        }
        __syncthreads();
    }

    const int tx = threadIdx.x;
    #pragma unroll
    for (int k = 0; k < 4; ++k) {
        int ty = threadIdx.y + k * 8;
        int y = y0 + ty, x = x0 + tx;
        int pix = y * IMG_W + x;
        float fgm = dacc_renorm(magA[k]).x;   // correctly-rounded fp32 grad_mag
        float fgx = dacc_renorm(gxsA[k]).x;
        float fgy = dacc_renorm(gysA[k]).x;
        // orient = atan2*(180/pi)+180 ; k = round(orient/45), half-to-even.
        float t  = atan2f(fgy, fgx);
        float o  = __fadd_rn(__fmul_rn(t, 57.29577951308232f), 180.0f);
        float kf = rintf(__fdiv_rn(o, 45.0f));       // in [0,8]
        int ip = ((int)kf) & 7;
        g_gmt[(size_t)pix * NB + b] = fgm;
        g_idx[(size_t)b * HW + pix] = (unsigned char)ip;
    }
}

// ---------------------------------------------------------------------------
// Kernel B: NMS (faithful cross-batch gather) + double threshold + hysteresis.
// Pure fp32 subtract/compare -> bit-exact given gm/idx.
// ---------------------------------------------------------------------------
__global__ __launch_bounds__(256) void canny_nms_kernel(float* __restrict__ out)
{
    const int b  = blockIdx.z;
    const int x0 = blockIdx.x * 32;
    const int y0 = blockIdx.y * 32;
    const int tid = threadIdx.y * 32 + threadIdx.x;

    __shared__ float s_gm[NB][36][38];   // 8 planes, halo 2
    __shared__ float s_thin[34][36];     // thin, halo 1

    for (int i = tid; i < 36 * 36; i += 256) {
        int r = i / 36, cc = i % 36;
        int y = y0 - 2 + r, x = x0 - 2 + cc;
        if ((unsigned)y < IMG_H && (unsigned)x < IMG_W) {
            const float4* p = reinterpret_cast<const float4*>(&g_gmt[(size_t)(y * IMG_W + x) * NB]);
            float4 v0 = p[0], v1 = p[1];
            s_gm[0][r][cc] = v0.x; s_gm[1][r][cc] = v0.y;
            s_gm[2][r][cc] = v0.z; s_gm[3][r][cc] = v0.w;
            s_gm[4][r][cc] = v1.x; s_gm[5][r][cc] = v1.y;
            s_gm[6][r][cc] = v1.z; s_gm[7][r][cc] = v1.w;
        } else {
            #pragma unroll
            for (int p = 0; p < 8; ++p) s_gm[p][r][cc] = 0.f;  // conv zero-pad
        }
    }
    __syncthreads();

    const int dy = c_dy[b], dx = c_dx[b];  // neighbor offset: uniform per batch

    for (int i = tid; i < 34 * 34; i += 256) {
        int r = i / 34, cc = i % 34;
        int y = y0 - 1 + r, x = x0 - 1 + cc;
        float thin = 0.f;
        if ((unsigned)y < IMG_H && (unsigned)x < IMG_W) {
            int pix = y * IMG_W + x;
            int ip  = g_idx[(size_t)b * HW + pix];
            int in_ = (ip + 4) & 7;
            int gr = r + 1, gc = cc + 1;
            float sp = __fsub_rn(s_gm[ip][gr][gc],  s_gm[ip][gr + dy][gc + dx]);
            float sn = __fsub_rn(s_gm[in_][gr][gc], s_gm[in_][gr + dy][gc + dx]);
            if (fminf(sp, sn) > 0.f) thin = s_gm[b][gr][gc];
        }
        s_thin[r][cc] = thin;
    }
    __syncthreads();

    const int tx = threadIdx.x;
    #pragma unroll
    for (int k = 0; k < 4; ++k) {
        int ty = threadIdx.y + k * 8;
        int y = y0 + ty, x = x0 + tx;
        float t = s_thin[ty + 1][tx + 1];
        float res;
        if (t > 5.0f) {
            res = 1.f;                               // strong
        } else if (t >= 2.5f) {                      // middle
            bool any =
                s_thin[ty][tx]     > 5.f || s_thin[ty][tx + 1]     > 5.f || s_thin[ty][tx + 2]     > 5.f ||
                s_thin[ty + 1][tx] > 5.f ||                                 s_thin[ty + 1][tx + 2] > 5.f ||
                s_thin[ty + 2][tx] > 5.f || s_thin[ty + 2][tx + 1] > 5.f || s_thin[ty + 2][tx + 2] > 5.f;
            res = any ? 1.f : 0.f;
        } else {
            res = 0.f;
        }
        if (y == 0 || y == IMG_H - 1 || x == 0 || x == IMG_W - 1) res = 0.f;
        out[(size_t)b * HW + y * IMG_W + x] = res;
    }
}

// ---------------------------------------------------------------------------
extern "C" void kernel_launch(void* const* d_in, const int* in_sizes, int n_in,
                              void* d_out, int out_size)
{
    const float* img   = (const float*)d_in[0];  // (8,3,1024,1024)
    const float* gauss = (const float*)d_in[1];  // gauss_h (1,1,1,5)
    (void)in_sizes; (void)n_in; (void)out_size;

    dim3 blk(32, 8);
    dim3 grid(IMG_W / 32, IMG_H / 32, NB);
    canny_grad_kernel<<<grid, blk>>>(img, gauss);
    canny_nms_kernel<<<grid, blk>>>((float*)d_out);
}